// round 16
// baseline (speedup 1.0000x reference)
#include <cuda_runtime.h>
#include <cstdint>

// Problem constants
#define BB 8
#define NN 16384
#define AA 7
#define GG 1024
#define KK 32

// Output layout (concatenated, float32)
#define NEIGH_OFF 0
#define CIDX_OFF  1835008
#define ATTR_OFF  1843200
#define COOR_OFF  1900544

#define FULLMASK 0xffffffffu

// Device scratch (no runtime allocation allowed)
__device__ float4 g_pts3[BB * NN];       // x,y,z,0         (FPS)
__device__ float4 g_ptsA[BB * NN * 2];   // a0..a3 | a4..a6,x2 (KNN)
__device__ int    g_cidx[BB * GG];
__device__ float  g_cent[BB * GG * 8];   // a0..a6, c2

// sum of 7 squares — XLA:GPU row-reduction emitter order (bit-exact, frozen):
//   ((p0+p4)+(p2+p6)) + ((p1+p5)+p3), separate mul.rn products.
__device__ __forceinline__ float sumsq7_shfltree(float a0, float a1, float a2, float a3,
                                                 float a4, float a5, float a6) {
    float p0 = __fmul_rn(a0, a0);
    float p1 = __fmul_rn(a1, a1);
    float p2 = __fmul_rn(a2, a2);
    float p3 = __fmul_rn(a3, a3);
    float p4 = __fmul_rn(a4, a4);
    float p5 = __fmul_rn(a5, a5);
    float p6 = __fmul_rn(a6, a6);
    float l = __fadd_rn(__fadd_rn(p0, p4), __fadd_rn(p2, p6));
    float r = __fadd_rn(__fadd_rn(p1, p5), p3);
    return __fadd_rn(l, r);
}

// ---- packed f32x2 helpers (Blackwell FFMA2 pipe; identical rn per lane) ----
#define MUL_F32X2(out, a, b) \
    asm("mul.rn.f32x2 %0, %1, %2;" : "=l"(out) : "l"(a), "l"(b))
#define ADD_F32X2(out, a, b) \
    asm("add.rn.f32x2 %0, %1, %2;" : "=l"(out) : "l"(a), "l"(b))
#define PACK_F32X2(out, lo, hi) \
    asm("mov.b64 %0, {%1, %2};" : "=l"(out) : "r"(__float_as_uint(lo)), "r"(__float_as_uint(hi)))
#define UNPACK_F32X2(lo, hi, in) \
    do { uint32_t _l, _h; \
         asm("mov.b64 {%0, %1}, %2;" : "=r"(_l), "=r"(_h) : "l"(in)); \
         lo = __uint_as_float(_l); hi = __uint_as_float(_h); } while (0)

// ---- cluster / mbarrier helpers --------------------------------------------
__device__ __forceinline__ uint32_t smem_u32(const void* p) {
    uint32_t a;
    asm("{ .reg .u64 t; cvta.to.shared.u64 t, %1; cvt.u32.u64 %0, t; }"
        : "=r"(a) : "l"(p));
    return a;
}
__device__ __forceinline__ uint32_t mapa_rank(uint32_t a, uint32_t r) {
    uint32_t o;
    asm("mapa.shared::cluster.u32 %0, %1, %2;" : "=r"(o) : "r"(a), "r"(r));
    return o;
}
__device__ __forceinline__ void mbar_init(uint32_t a, uint32_t cnt) {
    asm volatile("mbarrier.init.shared.b64 [%0], %1;" :: "r"(a), "r"(cnt) : "memory");
}
__device__ __forceinline__ void mbar_arrive_expect(uint32_t a, uint32_t tx) {
    asm volatile("mbarrier.arrive.expect_tx.shared.b64 _, [%0], %1;"
                 :: "r"(a), "r"(tx) : "memory");
}
__device__ __forceinline__ void mbar_wait(uint32_t a, uint32_t ph) {
    uint32_t done;
    asm volatile(
        "{\n\t.reg .pred p;\n\t"
        "mbarrier.try_wait.parity.acquire.cta.shared::cta.b64 p, [%1], %2;\n\t"
        "selp.b32 %0, 1, 0, p;\n\t}"
        : "=r"(done) : "r"(a), "r"(ph) : "memory");
    if (!done) {
        asm volatile(
            "{\n\t.reg .pred P1;\n\t"
            "WL_%=:\n\t"
            "mbarrier.try_wait.parity.acquire.cta.shared::cta.b64 P1, [%0], %1, 0x989680;\n\t"
            "@P1 bra.uni WD_%=;\n\t"
            "bra.uni WL_%=;\n\t"
            "WD_%=:\n\t}"
            :: "r"(a), "r"(ph) : "memory");
    }
}
__device__ __forceinline__ void st_async_b64(uint32_t raddr, unsigned long long v,
                                             uint32_t rmbar) {
    asm volatile(
        "st.async.shared::cluster.mbarrier::complete_tx::bytes.b64 [%0], %1, [%2];"
        :: "r"(raddr), "l"(v), "r"(rmbar) : "memory");
}
#define CLUSTER_SYNC() do { \
    asm volatile("barrier.cluster.arrive.aligned;" ::: "memory"); \
    asm volatile("barrier.cluster.wait.aligned;"   ::: "memory"); \
} while (0)

// ---------------------------------------------------------------------------
// Prep: pack points, precompute x2 (shuffle-tree order)
// ---------------------------------------------------------------------------
__global__ void prep_kernel(const float* __restrict__ xyz) {
    int i = blockIdx.x * blockDim.x + threadIdx.x;
    if (i >= BB * NN) return;
    const float* p = xyz + (size_t)i * AA;
    float a0 = p[0], a1 = p[1], a2 = p[2], a3 = p[3], a4 = p[4], a5 = p[5], a6 = p[6];
    float s = sumsq7_shfltree(a0, a1, a2, a3, a4, a5, a6);
    g_pts3[i] = make_float4(a0, a1, a2, 0.0f);
    g_ptsA[2 * i]     = make_float4(a0, a1, a2, a3);
    g_ptsA[2 * i + 1] = make_float4(a4, a5, a6, s);
}

// ---------------------------------------------------------------------------
// FPS v8 = v7 (R15, 648us) with key-only reduces EVERYWHERE (keys globally
// unique: disjoint idx ranges per CTA/thread). Level-1: key-only shfl, winner
// lane writes slot. Level-2 (pre-exchange): key-only, winner lane broadcasts
// coords via shfl-from-winner... simpler: winner lane is found by match; it
// writes its coords to s_wb* then lanes read — instead we shfl coords from
// the winning lane index. Final gather: key-only, matching lane writes s_c*.
// Frozen distance formula; exchange structure (24B x 8 msgs) unchanged.
// ---------------------------------------------------------------------------
__global__ void __launch_bounds__(256, 1) __cluster_dims__(8, 1, 1)
fps_kernel(float* __restrict__ out) {
    const int b = blockIdx.x >> 3;
    const uint32_t rank = blockIdx.x & 7;
    const int tid = threadIdx.x;
    const int lane = tid & 31, w = tid >> 5;

    __shared__ unsigned long long s_slotk[2][8];
    __shared__ unsigned long long s_slotxy[2][8];
    __shared__ unsigned long long s_slotz[2][8];
    __shared__ unsigned long long s_mbar[2];
    __shared__ unsigned long long s_wk[8];
    __shared__ float s_wx[8], s_wy[8], s_wz[8];
    __shared__ float s_cx, s_cy, s_cz;
    __shared__ int s_widx;

    const float4* pts = g_pts3 + b * NN;
    unsigned long long px2[4], py2[4], pz2[4];
    float px[8], py[8], pz[8], dist[8];
    uint32_t nidx[8];
#pragma unroll
    for (int j = 0; j < 8; ++j) {
        int idx = (int)rank * 2048 + j * 256 + tid;
        float4 p = pts[idx];
        px[j] = p.x; py[j] = p.y; pz[j] = p.z;
        dist[j] = 1e10f;
        nidx[j] = ~(uint32_t)idx;
    }
#pragma unroll
    for (int k = 0; k < 4; ++k) {
        PACK_F32X2(px2[k], px[2 * k], px[2 * k + 1]);
        PACK_F32X2(py2[k], py[2 * k], py[2 * k + 1]);
        PACK_F32X2(pz2[k], pz[2 * k], pz[2 * k + 1]);
    }

    const uint32_t mbar0 = smem_u32(&s_mbar[0]);
    const uint32_t mbar1 = smem_u32(&s_mbar[1]);

    if (tid == 0) {
        mbar_init(mbar0, 1);
        mbar_init(mbar1, 1);
        float4 c = pts[0];
        s_cx = c.x; s_cy = c.y; s_cz = c.z; s_widx = 0;
    }
    __syncthreads();
    CLUSTER_SYNC();   // remote mbarriers initialized before any st.async

    for (int t = 0; t < GG; ++t) {
        const int buf = t & 1;
        const uint32_t ph = (uint32_t)(t >> 1) & 1u;
        const uint32_t mbar = buf ? mbar1 : mbar0;

        if (tid == 0) {
            mbar_arrive_expect(mbar, 192);   // 8 CTAs x 24 bytes
            if (rank == 0) {
                int far = s_widx;
                g_cidx[b * GG + t] = far;
                out[CIDX_OFF + b * GG + t] = (float)far;
            }
        }
        const float cx = s_cx, cy = s_cy, cz = s_cz;
        const float ncx = -cx, ncy = -cy, ncz = -cz;
        unsigned long long ncx2, ncy2, ncz2;
        PACK_F32X2(ncx2, ncx, ncx);
        PACK_F32X2(ncy2, ncy, ncy);
        PACK_F32X2(ncz2, ncz, ncz);

        // update 8 dists via 4 packed pairs (frozen formula per lane)
        unsigned long long bk = 0; float bx = 0.f, by = 0.f, bz = 0.f;
#pragma unroll
        for (int k = 0; k < 4; ++k) {
            unsigned long long dx2, dy2, dz2, m1, m2, m3, s1, dp;
            ADD_F32X2(dx2, px2[k], ncx2);
            ADD_F32X2(dy2, py2[k], ncy2);
            ADD_F32X2(dz2, pz2[k], ncz2);
            MUL_F32X2(m1, dx2, dx2);
            MUL_F32X2(m3, dz2, dz2);
            ADD_F32X2(s1, m1, m3);
            MUL_F32X2(m2, dy2, dy2);
            ADD_F32X2(dp, s1, m2);
            float dlo, dhi;
            UNPACK_F32X2(dlo, dhi, dp);
            {
                int j = 2 * k;
                float nd = fminf(dist[j], dlo);
                dist[j] = nd;
                unsigned long long kk =
                    ((unsigned long long)__float_as_uint(nd) << 32) | nidx[j];
                if (kk > bk) { bk = kk; bx = px[j]; by = py[j]; bz = pz[j]; }
            }
            {
                int j = 2 * k + 1;
                float nd = fminf(dist[j], dhi);
                dist[j] = nd;
                unsigned long long kk =
                    ((unsigned long long)__float_as_uint(nd) << 32) | nidx[j];
                if (kk > bk) { bk = kk; bx = px[j]; by = py[j]; bz = pz[j]; }
            }
        }

        // key-only warp max reduce (keys unique -> exactly one winning lane)
        const unsigned long long mybk = bk;
#pragma unroll
        for (int off = 16; off > 0; off >>= 1) {
            unsigned long long ok = __shfl_down_sync(FULLMASK, bk, off);
            if (ok > bk) bk = ok;
        }
        bk = __shfl_sync(FULLMASK, bk, 0);
        if (mybk == bk) {
            s_wk[w] = bk; s_wx[w] = bx; s_wy[w] = by; s_wz[w] = bz;
        }
        __syncthreads();

        if (w == 0) {
            // level-2: key-only reduce over 8 warp slots
            unsigned long long wk = (lane < 8) ? s_wk[lane] : 0;
            const unsigned long long mywk = wk;
#pragma unroll
            for (int off = 4; off > 0; off >>= 1) {
                unsigned long long ok = __shfl_down_sync(FULLMASK, wk, off);
                if (ok > wk) wk = ok;
            }
            wk = __shfl_sync(FULLMASK, wk, 0);
            // winning lane (exactly one among lanes 0..7) loads its coords;
            // broadcast via ballot-derived source lane
            unsigned winmask = __ballot_sync(FULLMASK, (lane < 8) && (mywk == wk));
            int srcl = __ffs(winmask) - 1;
            float bx2 = 0.f, by2 = 0.f, bz2 = 0.f;
            if (lane == srcl) { bx2 = s_wx[lane]; by2 = s_wy[lane]; bz2 = s_wz[lane]; }
            bx2 = __shfl_sync(FULLMASK, bx2, srcl);
            by2 = __shfl_sync(FULLMASK, by2, srcl);
            bz2 = __shfl_sync(FULLMASK, bz2, srcl);

            if (lane < 8) {
                uint32_t rm   = mapa_rank(mbar, lane);
                uint32_t rak  = mapa_rank(smem_u32(&s_slotk[buf][rank]), lane);
                uint32_t raxy = mapa_rank(smem_u32(&s_slotxy[buf][rank]), lane);
                uint32_t raz  = mapa_rank(smem_u32(&s_slotz[buf][rank]), lane);
                unsigned long long xy =
                    ((unsigned long long)__float_as_uint(by2) << 32) | __float_as_uint(bx2);
                st_async_b64(rak, wk, rm);
                st_async_b64(raxy, xy, rm);
                st_async_b64(raz, (unsigned long long)__float_as_uint(bz2), rm);
            }

            mbar_wait(mbar, ph);

            // final gather: key-only reduce over 8 CTA slots; matching lane
            // reads its slot coords and writes the broadcast values.
            unsigned long long kk = (lane < 8) ? s_slotk[buf][lane] : 0;
            const unsigned long long mykk = kk;
#pragma unroll
            for (int off = 4; off > 0; off >>= 1) {
                unsigned long long ok = __shfl_down_sync(FULLMASK, kk, off);
                if (ok > kk) kk = ok;
            }
            kk = __shfl_sync(FULLMASK, kk, 0);
            if (lane < 8 && mykk == kk) {
                unsigned long long xy = s_slotxy[buf][lane];
                s_cx = __uint_as_float((uint32_t)xy);
                s_cy = __uint_as_float((uint32_t)(xy >> 32));
                s_cz = __uint_as_float((uint32_t)s_slotz[buf][lane]);
                s_widx = (int)(~(uint32_t)kk);
            }
        }
        __syncthreads();
    }
    CLUSTER_SYNC();   // no CTA exits while peers may still receive its stores
}

// ---------------------------------------------------------------------------
// Centroid gather: attrs + c2 (shuffle-tree order), write attrs/coors outputs
// ---------------------------------------------------------------------------
__global__ void cent_kernel(const float* __restrict__ xyz, float* __restrict__ out) {
    int g = blockIdx.x * blockDim.x + threadIdx.x;
    if (g >= BB * GG) return;
    int b = g / GG;
    int idx = g_cidx[g];
    const float* p = xyz + ((size_t)b * NN + idx) * AA;
    float a[7];
#pragma unroll
    for (int k = 0; k < 7; ++k) a[k] = p[k];
    float c2 = sumsq7_shfltree(a[0], a[1], a[2], a[3], a[4], a[5], a[6]);
#pragma unroll
    for (int k = 0; k < 7; ++k) {
        g_cent[g * 8 + k] = a[k];
        out[ATTR_OFF + (size_t)g * 7 + k] = a[k];
    }
    g_cent[g * 8 + 7] = c2;
#pragma unroll
    for (int k = 0; k < 3; ++k) out[COOR_OFF + (size_t)g * 3 + k] = a[k];
}

// ---------------------------------------------------------------------------
// KNN v2 (measured 224.5-225us x3): 512 blocks x 256 thr, 2 centroids/warp,
// 512-pt smem tiles, plain LDG->STS fill, queue tail cached in uniform regs
// (refreshed only on insert). Selection order-invariant; frozen arithmetic.
// ---------------------------------------------------------------------------
__device__ __forceinline__ void warp_q_insert_ballot(float& qd, int& qi,
                                                     float d2, int pi,
                                                     unsigned mm, int lane) {
    while (mm) {
        int src = __ffs(mm) - 1;
        mm &= mm - 1;
        float dd = __shfl_sync(FULLMASK, d2, src);
        int   ii = __shfl_sync(FULLMASK, pi, src);
        float pd = __shfl_up_sync(FULLMASK, qd, 1);
        int   px = __shfl_up_sync(FULLMASK, qi, 1);
        bool myGT = (qd > dd) || (qd == dd && qi > ii);
        bool prGT = (lane > 0) && ((pd > dd) || (pd == dd && px > ii));
        if (myGT) {
            qd = prGT ? pd : dd;
            qi = prGT ? px : ii;
        }
    }
}

__device__ __forceinline__ float dot7_fma_asc(const float* c, float4 pa, float4 pb) {
    float s = __fmul_rn(c[0], pa.x);
    s = __fmaf_rn(c[1], pa.y, s);
    s = __fmaf_rn(c[2], pa.z, s);
    s = __fmaf_rn(c[3], pa.w, s);
    s = __fmaf_rn(c[4], pb.x, s);
    s = __fmaf_rn(c[5], pb.y, s);
    s = __fmaf_rn(c[6], pb.z, s);
    return s;
}

__global__ void __launch_bounds__(256, 5) knn_kernel(float* __restrict__ out) {
    __shared__ float4 sA[512];
    __shared__ float4 sB[512];

    const int b = blockIdx.x >> 6;            // 64 blocks per batch
    const int gbase = (blockIdx.x & 63) * 16; // 16 centroids per block
    const int tid = threadIdx.x;
    const int w = tid >> 5, lane = tid & 31;

    const int g0 = b * GG + gbase + w * 2;
    const int g1 = g0 + 1;

    float ca[8], cb[8];
#pragma unroll
    for (int k = 0; k < 8; ++k) { ca[k] = g_cent[g0 * 8 + k]; cb[k] = g_cent[g1 * 8 + k]; }

    float qd0 = 3.4e38f, qd1 = 3.4e38f;
    int   qi0 = 0x7fffffff, qi1 = 0x7fffffff;
    float td0 = 3.4e38f, td1 = 3.4e38f;     // tail (lane31) cached uniformly
    int   ti0 = 0x7fffffff, ti1 = 0x7fffffff;

    const float4* base = g_ptsA + (size_t)b * NN * 2;

    for (int tile = 0; tile < 32; ++tile) {
        __syncthreads();
        for (int i = tid; i < 512; i += 256) {
            sA[i] = base[(size_t)(tile * 512 + i) * 2];
            sB[i] = base[(size_t)(tile * 512 + i) * 2 + 1];
        }
        __syncthreads();

#pragma unroll 4
        for (int step = 0; step < 16; ++step) {
            int pt = step * 32 + lane;
            float4 pa = sA[pt];
            float4 pb = sB[pt];
            int pi = tile * 512 + pt;

            {
                float dot = dot7_fma_asc(ca, pa, pb);
                float d2 = __fadd_rn(__fadd_rn(ca[7], pb.w), -__fmul_rn(2.0f, dot));
                bool pred = (d2 < td0) || (d2 == td0 && pi < ti0);
                unsigned mm = __ballot_sync(FULLMASK, pred);
                if (mm) {
                    warp_q_insert_ballot(qd0, qi0, d2, pi, mm, lane);
                    td0 = __shfl_sync(FULLMASK, qd0, 31);
                    ti0 = __shfl_sync(FULLMASK, qi0, 31);
                }
            }
            {
                float dot = dot7_fma_asc(cb, pa, pb);
                float d2 = __fadd_rn(__fadd_rn(cb[7], pb.w), -__fmul_rn(2.0f, dot));
                bool pred = (d2 < td1) || (d2 == td1 && pi < ti1);
                unsigned mm = __ballot_sync(FULLMASK, pred);
                if (mm) {
                    warp_q_insert_ballot(qd1, qi1, d2, pi, mm, lane);
                    td1 = __shfl_sync(FULLMASK, qd1, 31);
                    ti1 = __shfl_sync(FULLMASK, qi1, 31);
                }
            }
        }
    }

    // Emit neighborhoods: lane = rank within group (sorted ascending (d2, idx))
    {
        float4 pa = base[(size_t)qi0 * 2];
        float4 pb = base[(size_t)qi0 * 2 + 1];
        size_t o = ((size_t)g0 * KK + lane) * 7;
        out[o + 0] = __fadd_rn(pa.x, -ca[0]);
        out[o + 1] = __fadd_rn(pa.y, -ca[1]);
        out[o + 2] = __fadd_rn(pa.z, -ca[2]);
        out[o + 3] = pa.w;
        out[o + 4] = pb.x;
        out[o + 5] = pb.y;
        out[o + 6] = pb.z;
    }
    {
        float4 pa = base[(size_t)qi1 * 2];
        float4 pb = base[(size_t)qi1 * 2 + 1];
        size_t o = ((size_t)g1 * KK + lane) * 7;
        out[o + 0] = __fadd_rn(pa.x, -cb[0]);
        out[o + 1] = __fadd_rn(pa.y, -cb[1]);
        out[o + 2] = __fadd_rn(pa.z, -cb[2]);
        out[o + 3] = pa.w;
        out[o + 4] = pb.x;
        out[o + 5] = pb.y;
        out[o + 6] = pb.z;
    }
}

// ---------------------------------------------------------------------------
extern "C" void kernel_launch(void* const* d_in, const int* in_sizes, int n_in,
                              void* d_out, int out_size) {
    const float* xyz = (const float*)d_in[0];
    float* out = (float*)d_out;

    prep_kernel<<<(BB * NN + 255) / 256, 256>>>(xyz);
    fps_kernel<<<64, 256>>>(out);
    cent_kernel<<<(BB * GG + 255) / 256, 256>>>(xyz, out);
    knn_kernel<<<512, 256>>>(out);
}

// round 17
// speedup vs baseline: 1.1319x; 1.1319x over previous
#include <cuda_runtime.h>
#include <cstdint>

// Problem constants
#define BB 8
#define NN 16384
#define AA 7
#define GG 1024
#define KK 32

// Output layout (concatenated, float32)
#define NEIGH_OFF 0
#define CIDX_OFF  1835008
#define ATTR_OFF  1843200
#define COOR_OFF  1900544

#define FULLMASK 0xffffffffu

// Device scratch (no runtime allocation allowed)
__device__ float4 g_pts3[BB * NN];       // x,y,z,0         (FPS)
__device__ float4 g_ptsA[BB * NN * 2];   // a0..a3 | a4..a6,x2 (KNN)
__device__ int    g_cidx[BB * GG];
__device__ float  g_cent[BB * GG * 8];   // a0..a6, c2

// sum of 7 squares — XLA:GPU row-reduction emitter order (bit-exact, frozen):
//   ((p0+p4)+(p2+p6)) + ((p1+p5)+p3), separate mul.rn products.
__device__ __forceinline__ float sumsq7_shfltree(float a0, float a1, float a2, float a3,
                                                 float a4, float a5, float a6) {
    float p0 = __fmul_rn(a0, a0);
    float p1 = __fmul_rn(a1, a1);
    float p2 = __fmul_rn(a2, a2);
    float p3 = __fmul_rn(a3, a3);
    float p4 = __fmul_rn(a4, a4);
    float p5 = __fmul_rn(a5, a5);
    float p6 = __fmul_rn(a6, a6);
    float l = __fadd_rn(__fadd_rn(p0, p4), __fadd_rn(p2, p6));
    float r = __fadd_rn(__fadd_rn(p1, p5), p3);
    return __fadd_rn(l, r);
}

// ---- packed f32x2 helpers (Blackwell FFMA2 pipe; identical rn per lane) ----
#define MUL_F32X2(out, a, b) \
    asm("mul.rn.f32x2 %0, %1, %2;" : "=l"(out) : "l"(a), "l"(b))
#define ADD_F32X2(out, a, b) \
    asm("add.rn.f32x2 %0, %1, %2;" : "=l"(out) : "l"(a), "l"(b))
#define PACK_F32X2(out, lo, hi) \
    asm("mov.b64 %0, {%1, %2};" : "=l"(out) : "r"(__float_as_uint(lo)), "r"(__float_as_uint(hi)))
#define UNPACK_F32X2(lo, hi, in) \
    do { uint32_t _l, _h; \
         asm("mov.b64 {%0, %1}, %2;" : "=r"(_l), "=r"(_h) : "l"(in)); \
         lo = __uint_as_float(_l); hi = __uint_as_float(_h); } while (0)

// ---- cluster / mbarrier helpers --------------------------------------------
__device__ __forceinline__ uint32_t smem_u32(const void* p) {
    uint32_t a;
    asm("{ .reg .u64 t; cvta.to.shared.u64 t, %1; cvt.u32.u64 %0, t; }"
        : "=r"(a) : "l"(p));
    return a;
}
__device__ __forceinline__ uint32_t mapa_rank(uint32_t a, uint32_t r) {
    uint32_t o;
    asm("mapa.shared::cluster.u32 %0, %1, %2;" : "=r"(o) : "r"(a), "r"(r));
    return o;
}
__device__ __forceinline__ void mbar_init(uint32_t a, uint32_t cnt) {
    asm volatile("mbarrier.init.shared.b64 [%0], %1;" :: "r"(a), "r"(cnt) : "memory");
}
__device__ __forceinline__ void mbar_arrive_expect(uint32_t a, uint32_t tx) {
    asm volatile("mbarrier.arrive.expect_tx.shared.b64 _, [%0], %1;"
                 :: "r"(a), "r"(tx) : "memory");
}
__device__ __forceinline__ void mbar_wait(uint32_t a, uint32_t ph) {
    uint32_t done;
    asm volatile(
        "{\n\t.reg .pred p;\n\t"
        "mbarrier.try_wait.parity.acquire.cta.shared::cta.b64 p, [%1], %2;\n\t"
        "selp.b32 %0, 1, 0, p;\n\t}"
        : "=r"(done) : "r"(a), "r"(ph) : "memory");
    if (!done) {
        asm volatile(
            "{\n\t.reg .pred P1;\n\t"
            "WL_%=:\n\t"
            "mbarrier.try_wait.parity.acquire.cta.shared::cta.b64 P1, [%0], %1, 0x989680;\n\t"
            "@P1 bra.uni WD_%=;\n\t"
            "bra.uni WL_%=;\n\t"
            "WD_%=:\n\t}"
            :: "r"(a), "r"(ph) : "memory");
    }
}
__device__ __forceinline__ void st_async_b64(uint32_t raddr, unsigned long long v,
                                             uint32_t rmbar) {
    asm volatile(
        "st.async.shared::cluster.mbarrier::complete_tx::bytes.b64 [%0], %1, [%2];"
        :: "r"(raddr), "l"(v), "r"(rmbar) : "memory");
}
#define CLUSTER_SYNC() do { \
    asm volatile("barrier.cluster.arrive.aligned;" ::: "memory"); \
    asm volatile("barrier.cluster.wait.aligned;"   ::: "memory"); \
} while (0)

// ---------------------------------------------------------------------------
// Prep: pack points, precompute x2 (shuffle-tree order)
// ---------------------------------------------------------------------------
__global__ void prep_kernel(const float* __restrict__ xyz) {
    int i = blockIdx.x * blockDim.x + threadIdx.x;
    if (i >= BB * NN) return;
    const float* p = xyz + (size_t)i * AA;
    float a0 = p[0], a1 = p[1], a2 = p[2], a3 = p[3], a4 = p[4], a5 = p[5], a6 = p[6];
    float s = sumsq7_shfltree(a0, a1, a2, a3, a4, a5, a6);
    g_pts3[i] = make_float4(a0, a1, a2, 0.0f);
    g_ptsA[2 * i]     = make_float4(a0, a1, a2, a3);
    g_ptsA[2 * i + 1] = make_float4(a4, a5, a6, s);
}

// ---------------------------------------------------------------------------
// FPS v7 (R15-measured 648us): 8-CTA cluster per batch, 256 thr/CTA, 8 points
// per thread in registers, f32x2 packed distance update, key-only LEVEL-1
// warp reduce (winner lane writes slot), full carry reduce on w0 (level-2 and
// final gather — shuffles of independent values overlap in issue slots).
// st.async + mbarrier exchange, double-buffered. Frozen bit-exact formulas.
// ---------------------------------------------------------------------------
__global__ void __launch_bounds__(256, 1) __cluster_dims__(8, 1, 1)
fps_kernel(float* __restrict__ out) {
    const int b = blockIdx.x >> 3;
    const uint32_t rank = blockIdx.x & 7;
    const int tid = threadIdx.x;
    const int lane = tid & 31, w = tid >> 5;

    __shared__ unsigned long long s_slotk[2][8];
    __shared__ unsigned long long s_slotxy[2][8];
    __shared__ unsigned long long s_slotz[2][8];
    __shared__ unsigned long long s_mbar[2];
    __shared__ unsigned long long s_wk[8];
    __shared__ float s_wx[8], s_wy[8], s_wz[8];
    __shared__ float s_cx, s_cy, s_cz;
    __shared__ int s_widx;

    const float4* pts = g_pts3 + b * NN;
    unsigned long long px2[4], py2[4], pz2[4];
    float px[8], py[8], pz[8], dist[8];
    uint32_t nidx[8];
#pragma unroll
    for (int j = 0; j < 8; ++j) {
        int idx = (int)rank * 2048 + j * 256 + tid;
        float4 p = pts[idx];
        px[j] = p.x; py[j] = p.y; pz[j] = p.z;
        dist[j] = 1e10f;
        nidx[j] = ~(uint32_t)idx;
    }
#pragma unroll
    for (int k = 0; k < 4; ++k) {
        PACK_F32X2(px2[k], px[2 * k], px[2 * k + 1]);
        PACK_F32X2(py2[k], py[2 * k], py[2 * k + 1]);
        PACK_F32X2(pz2[k], pz[2 * k], pz[2 * k + 1]);
    }

    const uint32_t mbar0 = smem_u32(&s_mbar[0]);
    const uint32_t mbar1 = smem_u32(&s_mbar[1]);

    if (tid == 0) {
        mbar_init(mbar0, 1);
        mbar_init(mbar1, 1);
        float4 c = pts[0];
        s_cx = c.x; s_cy = c.y; s_cz = c.z; s_widx = 0;
    }
    __syncthreads();
    CLUSTER_SYNC();   // remote mbarriers initialized before any st.async

    for (int t = 0; t < GG; ++t) {
        const int buf = t & 1;
        const uint32_t ph = (uint32_t)(t >> 1) & 1u;
        const uint32_t mbar = buf ? mbar1 : mbar0;

        if (tid == 0) {
            mbar_arrive_expect(mbar, 192);   // 8 CTAs x 24 bytes
            if (rank == 0) {
                int far = s_widx;
                g_cidx[b * GG + t] = far;
                out[CIDX_OFF + b * GG + t] = (float)far;
            }
        }
        const float cx = s_cx, cy = s_cy, cz = s_cz;
        const float ncx = -cx, ncy = -cy, ncz = -cz;
        unsigned long long ncx2, ncy2, ncz2;
        PACK_F32X2(ncx2, ncx, ncx);
        PACK_F32X2(ncy2, ncy, ncy);
        PACK_F32X2(ncz2, ncz, ncz);

        // update 8 dists via 4 packed pairs (frozen formula per lane)
        unsigned long long bk = 0; float bx = 0.f, by = 0.f, bz = 0.f;
#pragma unroll
        for (int k = 0; k < 4; ++k) {
            unsigned long long dx2, dy2, dz2, m1, m2, m3, s1, dp;
            ADD_F32X2(dx2, px2[k], ncx2);
            ADD_F32X2(dy2, py2[k], ncy2);
            ADD_F32X2(dz2, pz2[k], ncz2);
            MUL_F32X2(m1, dx2, dx2);
            MUL_F32X2(m3, dz2, dz2);
            ADD_F32X2(s1, m1, m3);
            MUL_F32X2(m2, dy2, dy2);
            ADD_F32X2(dp, s1, m2);
            float dlo, dhi;
            UNPACK_F32X2(dlo, dhi, dp);
            {
                int j = 2 * k;
                float nd = fminf(dist[j], dlo);
                dist[j] = nd;
                unsigned long long kk =
                    ((unsigned long long)__float_as_uint(nd) << 32) | nidx[j];
                if (kk > bk) { bk = kk; bx = px[j]; by = py[j]; bz = pz[j]; }
            }
            {
                int j = 2 * k + 1;
                float nd = fminf(dist[j], dhi);
                dist[j] = nd;
                unsigned long long kk =
                    ((unsigned long long)__float_as_uint(nd) << 32) | nidx[j];
                if (kk > bk) { bk = kk; bx = px[j]; by = py[j]; bz = pz[j]; }
            }
        }

        // key-only warp max reduce (keys unique -> exactly one winning lane)
        const unsigned long long mybk = bk;
#pragma unroll
        for (int off = 16; off > 0; off >>= 1) {
            unsigned long long ok = __shfl_down_sync(FULLMASK, bk, off);
            if (ok > bk) bk = ok;
        }
        bk = __shfl_sync(FULLMASK, bk, 0);
        if (mybk == bk) {
            s_wk[w] = bk; s_wx[w] = bx; s_wy[w] = by; s_wz[w] = bz;
        }
        __syncthreads();

        if (w == 0) {
            if (lane < 8) {
                bk = s_wk[lane]; bx = s_wx[lane]; by = s_wy[lane]; bz = s_wz[lane];
            } else bk = 0;
#pragma unroll
            for (int off = 4; off > 0; off >>= 1) {
                unsigned long long ok = __shfl_down_sync(FULLMASK, bk, off);
                float ox = __shfl_down_sync(FULLMASK, bx, off);
                float oy = __shfl_down_sync(FULLMASK, by, off);
                float oz = __shfl_down_sync(FULLMASK, bz, off);
                if (ok > bk) { bk = ok; bx = ox; by = oy; bz = oz; }
            }
            bk = __shfl_sync(FULLMASK, bk, 0);
            bx = __shfl_sync(FULLMASK, bx, 0);
            by = __shfl_sync(FULLMASK, by, 0);
            bz = __shfl_sync(FULLMASK, bz, 0);

            if (lane < 8) {
                uint32_t rm   = mapa_rank(mbar, lane);
                uint32_t rak  = mapa_rank(smem_u32(&s_slotk[buf][rank]), lane);
                uint32_t raxy = mapa_rank(smem_u32(&s_slotxy[buf][rank]), lane);
                uint32_t raz  = mapa_rank(smem_u32(&s_slotz[buf][rank]), lane);
                unsigned long long xy =
                    ((unsigned long long)__float_as_uint(by) << 32) | __float_as_uint(bx);
                st_async_b64(rak, bk, rm);
                st_async_b64(raxy, xy, rm);
                st_async_b64(raz, (unsigned long long)__float_as_uint(bz), rm);
            }

            mbar_wait(mbar, ph);

            unsigned long long kk = 0; float xx = 0.f, yy = 0.f, zz = 0.f;
            if (lane < 8) {
                kk = s_slotk[buf][lane];
                unsigned long long xy = s_slotxy[buf][lane];
                xx = __uint_as_float((uint32_t)xy);
                yy = __uint_as_float((uint32_t)(xy >> 32));
                zz = __uint_as_float((uint32_t)s_slotz[buf][lane]);
            }
#pragma unroll
            for (int off = 4; off > 0; off >>= 1) {
                unsigned long long ok = __shfl_down_sync(FULLMASK, kk, off);
                float ox = __shfl_down_sync(FULLMASK, xx, off);
                float oy = __shfl_down_sync(FULLMASK, yy, off);
                float oz = __shfl_down_sync(FULLMASK, zz, off);
                if (ok > kk) { kk = ok; xx = ox; yy = oy; zz = oz; }
            }
            if (lane == 0) {
                s_cx = xx; s_cy = yy; s_cz = zz;
                s_widx = (int)(~(uint32_t)kk);
            }
        }
        __syncthreads();
    }
    CLUSTER_SYNC();   // no CTA exits while peers may still receive its stores
}

// ---------------------------------------------------------------------------
// Centroid gather: attrs + c2 (shuffle-tree order), write attrs/coors outputs
// ---------------------------------------------------------------------------
__global__ void cent_kernel(const float* __restrict__ xyz, float* __restrict__ out) {
    int g = blockIdx.x * blockDim.x + threadIdx.x;
    if (g >= BB * GG) return;
    int b = g / GG;
    int idx = g_cidx[g];
    const float* p = xyz + ((size_t)b * NN + idx) * AA;
    float a[7];
#pragma unroll
    for (int k = 0; k < 7; ++k) a[k] = p[k];
    float c2 = sumsq7_shfltree(a[0], a[1], a[2], a[3], a[4], a[5], a[6]);
#pragma unroll
    for (int k = 0; k < 7; ++k) {
        g_cent[g * 8 + k] = a[k];
        out[ATTR_OFF + (size_t)g * 7 + k] = a[k];
    }
    g_cent[g * 8 + 7] = c2;
#pragma unroll
    for (int k = 0; k < 3; ++k) out[COOR_OFF + (size_t)g * 3 + k] = a[k];
}

// ---------------------------------------------------------------------------
// KNN v2 (measured 224.5-226us x4): 512 blocks x 256 thr, 2 centroids/warp,
// 512-pt smem tiles, plain LDG->STS fill, queue tail cached in uniform regs
// (refreshed only on insert). Selection order-invariant; frozen arithmetic.
// ---------------------------------------------------------------------------
__device__ __forceinline__ void warp_q_insert_ballot(float& qd, int& qi,
                                                     float d2, int pi,
                                                     unsigned mm, int lane) {
    while (mm) {
        int src = __ffs(mm) - 1;
        mm &= mm - 1;
        float dd = __shfl_sync(FULLMASK, d2, src);
        int   ii = __shfl_sync(FULLMASK, pi, src);
        float pd = __shfl_up_sync(FULLMASK, qd, 1);
        int   px = __shfl_up_sync(FULLMASK, qi, 1);
        bool myGT = (qd > dd) || (qd == dd && qi > ii);
        bool prGT = (lane > 0) && ((pd > dd) || (pd == dd && px > ii));
        if (myGT) {
            qd = prGT ? pd : dd;
            qi = prGT ? px : ii;
        }
    }
}

__device__ __forceinline__ float dot7_fma_asc(const float* c, float4 pa, float4 pb) {
    float s = __fmul_rn(c[0], pa.x);
    s = __fmaf_rn(c[1], pa.y, s);
    s = __fmaf_rn(c[2], pa.z, s);
    s = __fmaf_rn(c[3], pa.w, s);
    s = __fmaf_rn(c[4], pb.x, s);
    s = __fmaf_rn(c[5], pb.y, s);
    s = __fmaf_rn(c[6], pb.z, s);
    return s;
}

__global__ void __launch_bounds__(256, 5) knn_kernel(float* __restrict__ out) {
    __shared__ float4 sA[512];
    __shared__ float4 sB[512];

    const int b = blockIdx.x >> 6;            // 64 blocks per batch
    const int gbase = (blockIdx.x & 63) * 16; // 16 centroids per block
    const int tid = threadIdx.x;
    const int w = tid >> 5, lane = tid & 31;

    const int g0 = b * GG + gbase + w * 2;
    const int g1 = g0 + 1;

    float ca[8], cb[8];
#pragma unroll
    for (int k = 0; k < 8; ++k) { ca[k] = g_cent[g0 * 8 + k]; cb[k] = g_cent[g1 * 8 + k]; }

    float qd0 = 3.4e38f, qd1 = 3.4e38f;
    int   qi0 = 0x7fffffff, qi1 = 0x7fffffff;
    float td0 = 3.4e38f, td1 = 3.4e38f;     // tail (lane31) cached uniformly
    int   ti0 = 0x7fffffff, ti1 = 0x7fffffff;

    const float4* base = g_ptsA + (size_t)b * NN * 2;

    for (int tile = 0; tile < 32; ++tile) {
        __syncthreads();
        for (int i = tid; i < 512; i += 256) {
            sA[i] = base[(size_t)(tile * 512 + i) * 2];
            sB[i] = base[(size_t)(tile * 512 + i) * 2 + 1];
        }
        __syncthreads();

#pragma unroll 4
        for (int step = 0; step < 16; ++step) {
            int pt = step * 32 + lane;
            float4 pa = sA[pt];
            float4 pb = sB[pt];
            int pi = tile * 512 + pt;

            {
                float dot = dot7_fma_asc(ca, pa, pb);
                float d2 = __fadd_rn(__fadd_rn(ca[7], pb.w), -__fmul_rn(2.0f, dot));
                bool pred = (d2 < td0) || (d2 == td0 && pi < ti0);
                unsigned mm = __ballot_sync(FULLMASK, pred);
                if (mm) {
                    warp_q_insert_ballot(qd0, qi0, d2, pi, mm, lane);
                    td0 = __shfl_sync(FULLMASK, qd0, 31);
                    ti0 = __shfl_sync(FULLMASK, qi0, 31);
                }
            }
            {
                float dot = dot7_fma_asc(cb, pa, pb);
                float d2 = __fadd_rn(__fadd_rn(cb[7], pb.w), -__fmul_rn(2.0f, dot));
                bool pred = (d2 < td1) || (d2 == td1 && pi < ti1);
                unsigned mm = __ballot_sync(FULLMASK, pred);
                if (mm) {
                    warp_q_insert_ballot(qd1, qi1, d2, pi, mm, lane);
                    td1 = __shfl_sync(FULLMASK, qd1, 31);
                    ti1 = __shfl_sync(FULLMASK, qi1, 31);
                }
            }
        }
    }

    // Emit neighborhoods: lane = rank within group (sorted ascending (d2, idx))
    {
        float4 pa = base[(size_t)qi0 * 2];
        float4 pb = base[(size_t)qi0 * 2 + 1];
        size_t o = ((size_t)g0 * KK + lane) * 7;
        out[o + 0] = __fadd_rn(pa.x, -ca[0]);
        out[o + 1] = __fadd_rn(pa.y, -ca[1]);
        out[o + 2] = __fadd_rn(pa.z, -ca[2]);
        out[o + 3] = pa.w;
        out[o + 4] = pb.x;
        out[o + 5] = pb.y;
        out[o + 6] = pb.z;
    }
    {
        float4 pa = base[(size_t)qi1 * 2];
        float4 pb = base[(size_t)qi1 * 2 + 1];
        size_t o = ((size_t)g1 * KK + lane) * 7;
        out[o + 0] = __fadd_rn(pa.x, -cb[0]);
        out[o + 1] = __fadd_rn(pa.y, -cb[1]);
        out[o + 2] = __fadd_rn(pa.z, -cb[2]);
        out[o + 3] = pa.w;
        out[o + 4] = pb.x;
        out[o + 5] = pb.y;
        out[o + 6] = pb.z;
    }
}

// ---------------------------------------------------------------------------
extern "C" void kernel_launch(void* const* d_in, const int* in_sizes, int n_in,
                              void* d_out, int out_size) {
    const float* xyz = (const float*)d_in[0];
    float* out = (float*)d_out;

    prep_kernel<<<(BB * NN + 255) / 256, 256>>>(xyz);
    fps_kernel<<<64, 256>>>(out);
    cent_kernel<<<(BB * GG + 255) / 256, 256>>>(xyz, out);
    knn_kernel<<<512, 256>>>(out);
}